// round 1
// baseline (speedup 1.0000x reference)
#include <cuda_runtime.h>
#include <cuda_bf16.h>

// Problem constants
// B=32, Cin=11, H=W=128, K=8, P=7, TN=16, ED=64, SD=32
// out: (32, 64, 128, 128) float32

// ---------------- static device scratch (no allocs allowed) ----------------
__device__ float g_TW[12 * 9 * 64];        // tap weights per class (class 11 = pad = 0)
__device__ float g_AT[64 * 64];            // A^T: AT[k][o] = A[o][k],  A = (I+W1)@conv2_w
__device__ float g_D[8 * 8 * 64];          // D[hm][wm][o] constant term
__device__ float g_Fs[10 * 10 * 12 * 64];  // singles:  [ht][wt][c_cur][o]
__device__ float g_Fr[10 * 12 * 12 * 64];  // ht==8 :   [wt][c_cur][c_below][o]
__device__ float g_Fc[10 * 12 * 12 * 64];  // wt==8 :   [ht][c_cur][c_right][o]
__device__ int   g_lab[32 * 16 * 16];      // per-tile class labels

// patch-row kinds per position type t (0..9), dy index 0..2 (-1,0,+1)
// 0=PAD, 1=ZERO(class0 gutter), 2=CUR tile, 3=NEXT tile
__constant__ int c_rk[10][3] = {
    {0,2,2}, // h==0      (hm=0, top edge)
    {1,2,2}, // hm=0, h>0
    {2,2,2}, // hm=1
    {2,2,2}, // hm=2
    {2,2,2}, // hm=3
    {2,2,2}, // hm=4
    {2,2,2}, // hm=5
    {2,2,1}, // hm=6
    {2,1,3}, // hm=7, h<127
    {2,1,0}  // h==127
};

__device__ __forceinline__ int cellcls(int rk, int ck, int cc, int cr, int cb, int cd) {
    if (rk == 0 || ck == 0) return 11;   // pad
    if (rk == 1 || ck == 1) return 0;    // background gutter
    if (rk == 2) return (ck == 2) ? cc : cr;
    return (ck == 2) ? cb : cd;
}

__device__ __forceinline__ int hm_of(int t) { return (t <= 1) ? 0 : ((t <= 7) ? t - 1 : 7); }

// ---------------- kernel 1: tiny setup (shape encoder, A, D, TW) ----------------
__global__ void setup_kernel(const float* __restrict__ c1w, const float* __restrict__ c1b,
                             const float* __restrict__ c2w, const float* __restrict__ c2b,
                             const float* __restrict__ sew, const float* __restrict__ seb,
                             const float* __restrict__ slw, const float* __restrict__ slb,
                             const float* __restrict__ rpw, const float* __restrict__ rpb,
                             const float* __restrict__ fw,  const float* __restrict__ fb)
{
    __shared__ float sh_h[16 * 49];
    __shared__ float sh_p[256];
    __shared__ float sh_sv[32];
    __shared__ float sh_pos[32 * 49];
    int tid = threadIdx.x; // 256 threads

    // se conv3x3 on all-ones 7x7 mask, pad=1, relu
    for (int idx = tid; idx < 16 * 49; idx += 256) {
        int c = idx / 49, r = (idx % 49) / 7, j = idx % 7;
        float v = seb[c];
        for (int ky = 0; ky < 3; ky++)
            for (int kx = 0; kx < 3; kx++) {
                int rr = r - 1 + ky, ccol = j - 1 + kx;
                if (rr >= 0 && rr < 7 && ccol >= 0 && ccol < 7) v += sew[c * 9 + ky * 3 + kx];
            }
        sh_h[idx] = fmaxf(v, 0.f);
    }
    __syncthreads();

    // adaptive maxpool 7->4
    {
        int c = tid / 16, ri = (tid % 16) / 4, rj = tid % 4;
        const int s4[4] = {0, 1, 3, 5}, e4[4] = {2, 4, 6, 7};
        float m = -1e30f;
        for (int r = s4[ri]; r < e4[ri]; r++)
            for (int cc = s4[rj]; cc < e4[rj]; cc++)
                m = fmaxf(m, sh_h[c * 49 + r * 7 + cc]);
        sh_p[tid] = m;
    }
    __syncthreads();

    // shape_vec
    if (tid < 32) {
        float a = slb[tid];
        for (int t = 0; t < 256; t++) a += slw[tid * 256 + t] * sh_p[t];
        sh_sv[tid] = fmaxf(a, 0.f);
    }
    // pos
    for (int idx = tid; idx < 32 * 49; idx += 256) {
        int s = idx / 49, i = (idx % 49) / 7, j = idx % 7;
        sh_pos[idx] = rpb[s] + rpw[s * 2] * (i / 6.0f) + rpw[s * 2 + 1] * (j / 6.0f);
    }
    __syncthreads();

    // AT[k][o] = conv2_w[o][k] + sum_m fus_w[o][m]*conv2_w[m][k]
    for (int p = tid; p < 4096; p += 256) {
        int o = p >> 6, k = p & 63;
        float a = c2w[o * 64 + k];
        for (int m = 0; m < 64; m++) a += fw[o * 128 + m] * c2w[m * 64 + k];
        g_AT[k * 64 + o] = a;
    }
    // D[hm][wm][o]
    for (int p = tid; p < 4096; p += 256) {
        int hm = p >> 9, wm = (p >> 6) & 7, o = p & 63;
        float d = c2b[o] + fb[o];
        for (int m = 0; m < 64; m++) d += fw[o * 128 + m] * c2b[m];
        if (hm < 7 && wm < 7) {
            for (int s = 0; s < 32; s++) d += fw[o * 128 + 64 + s] * sh_sv[s];
            for (int s = 0; s < 32; s++) d += fw[o * 128 + 96 + s] * sh_pos[s * 49 + hm * 7 + wm];
        }
        g_D[p] = d;
    }
    // TW[class][tap][o]
    for (int idx = tid; idx < 12 * 9 * 64; idx += 256) {
        int c = idx / (9 * 64), t = (idx / 64) % 9, o = idx & 63;
        g_TW[idx] = (c < 11) ? c1w[o * 99 + c * 9 + t] : 0.f;
    }
}

// ---------------- kernel 2: per-tile labels from one-hot x ----------------
__global__ void label_kernel(const float* __restrict__ x) {
    int idx = blockIdx.x * blockDim.x + threadIdx.x;
    if (idx >= 32 * 256) return;
    int b = idx >> 8, ty = (idx >> 4) & 15, tx = idx & 15;
    const float* px = x + (long long)b * 11 * 16384 + (ty * 8) * 128 + (tx * 8);
    int best = 0; float bv = px[0];
    for (int c = 1; c < 11; c++) {
        float v = px[(long long)c * 16384];
        if (v > bv) { bv = v; best = c; }
    }
    g_lab[idx] = best;
}

// ---------------- kernel 3: build final-value tables ----------------
__global__ void table_kernel(const float* __restrict__ c1b) {
    __shared__ float sy[64];
    int e = blockIdx.x, o = threadIdx.x;
    int ht, wt, cc, cr = 11, cb = 11, cd = 11;
    float* dst;
    if (e < 972) {
        cc = e % 12; int r = e / 12;
        int wi = r % 9, hi = r / 9;
        wt = (wi == 8) ? 9 : wi;
        ht = (hi == 8) ? 9 : hi;
        dst = &g_Fs[((ht * 10 + wt) * 12 + cc) * 64];
    } else if (e < 972 + 1296) {
        int r = e - 972;
        cb = r % 12; r /= 12; cc = r % 12;
        int wi = r / 12; wt = (wi == 8) ? 9 : wi; ht = 8;
        dst = &g_Fr[((wt * 12 + cc) * 12 + cb) * 64];
    } else {
        int r = e - 972 - 1296;
        cr = r % 12; r /= 12; cc = r % 12;
        int hi = r / 12; ht = (hi == 8) ? 9 : hi; wt = 8;
        dst = &g_Fc[((ht * 12 + cc) * 12 + cr) * 64];
    }
    float y = c1b[o];
    #pragma unroll
    for (int dy = 0; dy < 3; dy++)
        #pragma unroll
        for (int dx = 0; dx < 3; dx++) {
            int rk = c_rk[ht][dy], ck = c_rk[wt][dx];
            int cls = cellcls(rk, ck, cc, cr, cb, cd);
            y += g_TW[(cls * 9 + dy * 3 + dx) * 64 + o];
        }
    sy[o] = fmaxf(y, 0.f);
    __syncthreads();
    int hm = hm_of(ht), wm = hm_of(wt);
    float acc = g_D[(hm * 8 + wm) * 64 + o];
    #pragma unroll 8
    for (int k = 0; k < 64; k++) acc += g_AT[k * 64 + o] * sy[k];
    dst[o] = acc;
}

// ---------------- kernel 4: main gather + write ----------------
__global__ void main_kernel(float* __restrict__ out) {
    int p = blockIdx.x * 128 + threadIdx.x;
    int b = p >> 14, rem = p & 16383, h = rem >> 7, w = rem & 127;
    int hm = h & 7, wm = w & 7;
    int ht = (hm == 0) ? (h == 0 ? 0 : 1) : (hm < 7 ? hm + 1 : (h == 127 ? 9 : 8));
    int wt = (wm == 0) ? (w == 0 ? 0 : 1) : (wm < 7 ? wm + 1 : (w == 127 ? 9 : 8));
    int ty = h >> 3, tx = w >> 3;
    int labbase = (b << 8) + (ty << 4) + tx;
    int cc = g_lab[labbase];
    const float4* F;
    if (ht == 8) {
        if (wt == 8) return;  // tile-corner pixels: corner_kernel writes them
        int cb = g_lab[labbase + 16];
        F = (const float4*)&g_Fr[((wt * 12 + cc) * 12 + cb) * 64];
    } else if (wt == 8) {
        int cr = g_lab[labbase + 1];
        F = (const float4*)&g_Fc[((ht * 12 + cc) * 12 + cr) * 64];
    } else {
        F = (const float4*)&g_Fs[((ht * 10 + wt) * 12 + cc) * 64];
    }
    float* op = out + ((long long)b << 20) + rem;
    #pragma unroll
    for (int q = 0; q < 16; q++) {
        float4 v = F[q];
        op[(4 * q + 0) * 16384] = v.x;
        op[(4 * q + 1) * 16384] = v.y;
        op[(4 * q + 2) * 16384] = v.z;
        op[(4 * q + 3) * 16384] = v.w;
    }
}

// ---------------- kernel 5: tile-corner pixels (4-class dependency) ----------------
__global__ void corner_kernel(const float* __restrict__ c1b, float* __restrict__ out) {
    __shared__ float sy[64];
    int e = blockIdx.x, o = threadIdx.x;
    int b = e / 225, r = e % 225, ti = r / 15, tj = r % 15;
    int labbase = (b << 8) + (ti << 4) + tj;
    int cc = g_lab[labbase], cr = g_lab[labbase + 1];
    int cb = g_lab[labbase + 16], cd = g_lab[labbase + 17];
    float y = c1b[o];
    #pragma unroll
    for (int dy = 0; dy < 3; dy++)
        #pragma unroll
        for (int dx = 0; dx < 3; dx++) {
            int rk = c_rk[8][dy], ck = c_rk[8][dx];
            int cls = cellcls(rk, ck, cc, cr, cb, cd);
            y += g_TW[(cls * 9 + dy * 3 + dx) * 64 + o];
        }
    sy[o] = fmaxf(y, 0.f);
    __syncthreads();
    float acc = g_D[(7 * 8 + 7) * 64 + o];
    #pragma unroll 8
    for (int k = 0; k < 64; k++) acc += g_AT[k * 64 + o] * sy[k];
    int h = ti * 8 + 7, w = tj * 8 + 7;
    out[((long long)(b * 64 + o) << 14) + h * 128 + w] = acc;
}

// ---------------- launch ----------------
extern "C" void kernel_launch(void* const* d_in, const int* in_sizes, int n_in,
                              void* d_out, int out_size) {
    const float* x   = (const float*)d_in[0];
    const float* c1w = (const float*)d_in[1];
    const float* c1b = (const float*)d_in[2];
    const float* c2w = (const float*)d_in[3];
    const float* c2b = (const float*)d_in[4];
    const float* sew = (const float*)d_in[5];
    const float* seb = (const float*)d_in[6];
    const float* slw = (const float*)d_in[7];
    const float* slb = (const float*)d_in[8];
    const float* rpw = (const float*)d_in[9];
    const float* rpb = (const float*)d_in[10];
    const float* fw  = (const float*)d_in[11];
    const float* fb  = (const float*)d_in[12];
    float* out = (float*)d_out;

    setup_kernel<<<1, 256>>>(c1w, c1b, c2w, c2b, sew, seb, slw, slb, rpw, rpb, fw, fb);
    label_kernel<<<64, 128>>>(x);
    table_kernel<<<972 + 1296 + 1296, 64>>>(c1b);
    main_kernel<<<4096, 128>>>(out);
    corner_kernel<<<32 * 225, 64>>>(c1b, out);
}

// round 2
// speedup vs baseline: 2.7461x; 2.7461x over previous
#include <cuda_runtime.h>
#include <cuda_bf16.h>

// Problem constants: B=32, Cin=11, H=W=128, K=8, P=7, TN=16, ED=64, SD=32
// out: (32, 64, 128, 128) float32

// ---------------- static device scratch ----------------
__device__ __align__(256) float g_TW[12 * 9 * 64];        // tap weights per class (11 = pad = 0)
__device__ __align__(256) float g_AT[64 * 64];            // AT[k][o], A = (I+W1)@conv2_w
__device__ __align__(256) float g_D[8 * 8 * 64];          // D[hm][wm][o]
__device__ __align__(256) float g_Fs[10 * 10 * 12 * 64];  // [ht][wt][cc][o]
__device__ __align__(256) float g_Fr[10 * 12 * 12 * 64];  // ht==8: [wt][cc][cb][o]
__device__ __align__(256) float g_Fc[10 * 12 * 12 * 64];  // wt==8: [ht][cc][cr][o]
__device__ int   g_lab[32 * 16 * 16];

// row kinds per position type t (0..9): 0=PAD,1=ZERO,2=CUR,3=NEXT
__constant__ int c_rk[10][3] = {
    {0,2,2},{1,2,2},{2,2,2},{2,2,2},{2,2,2},{2,2,2},{2,2,2},{2,2,1},{2,1,3},{2,1,0}
};

__device__ __forceinline__ int cellcls(int rk, int ck, int cc, int cr, int cb, int cd) {
    if (rk == 0 || ck == 0) return 11;
    if (rk == 1 || ck == 1) return 0;
    if (rk == 2) return (ck == 2) ? cc : cr;
    return (ck == 2) ? cb : cd;
}
__device__ __forceinline__ int hm_of(int t) { return (t <= 1) ? 0 : ((t <= 7) ? t - 1 : 7); }

// ================= K1: setup (parallel) + labels =================
// blocks 0..15: D (with small prolog), 16..31: AT, 32..59: TW, 60..91: labels
__global__ void k1_kernel(const float* __restrict__ x,
                          const float* __restrict__ c1w, const float* __restrict__ c1b,
                          const float* __restrict__ c2w, const float* __restrict__ c2b,
                          const float* __restrict__ sew, const float* __restrict__ seb,
                          const float* __restrict__ slw, const float* __restrict__ slb,
                          const float* __restrict__ rpw, const float* __restrict__ rpb,
                          const float* __restrict__ fw,  const float* __restrict__ fb)
{
    int tid = threadIdx.x;
    int blk = blockIdx.x;

    if (blk < 16) {
        // ---- prolog: shape_vec + pos (redundant per block, cheap) ----
        __shared__ float sh_h[16 * 49];
        __shared__ float sh_p[256];
        __shared__ float sh_sv[32];
        __shared__ float sh_pos[32 * 49];

        for (int idx = tid; idx < 16 * 49; idx += 256) {
            int c = idx / 49, r = (idx % 49) / 7, j = idx % 7;
            float v = seb[c];
            for (int ky = 0; ky < 3; ky++)
                for (int kx = 0; kx < 3; kx++) {
                    int rr = r - 1 + ky, ccol = j - 1 + kx;
                    if (rr >= 0 && rr < 7 && ccol >= 0 && ccol < 7) v += sew[c * 9 + ky * 3 + kx];
                }
            sh_h[idx] = fmaxf(v, 0.f);
        }
        __syncthreads();
        {
            int c = tid / 16, ri = (tid % 16) / 4, rj = tid % 4;
            const int s4[4] = {0, 1, 3, 5}, e4[4] = {2, 4, 6, 7};
            float m = -1e30f;
            for (int r = s4[ri]; r < e4[ri]; r++)
                for (int cc = s4[rj]; cc < e4[rj]; cc++)
                    m = fmaxf(m, sh_h[c * 49 + r * 7 + cc]);
            sh_p[tid] = m;
        }
        __syncthreads();
        if (tid < 32) {
            float a = slb[tid];
            for (int t = 0; t < 256; t++) a += slw[tid * 256 + t] * sh_p[t];
            sh_sv[tid] = fmaxf(a, 0.f);
        }
        for (int idx = tid; idx < 32 * 49; idx += 256) {
            int s = idx / 49, i = (idx % 49) / 7, j = idx % 7;
            sh_pos[idx] = rpb[s] + rpw[s * 2] * (i / 6.0f) + rpw[s * 2 + 1] * (j / 6.0f);
        }
        __syncthreads();
        // ---- D entry (one per thread) ----
        int p = blk * 256 + tid;  // < 4096
        int hm = p >> 9, wm = (p >> 6) & 7, o = p & 63;
        float d = c2b[o] + fb[o];
        #pragma unroll 8
        for (int m = 0; m < 64; m++) d += fw[o * 128 + m] * c2b[m];
        if (hm < 7 && wm < 7) {
            for (int s = 0; s < 32; s++) d += fw[o * 128 + 64 + s] * sh_sv[s];
            for (int s = 0; s < 32; s++) d += fw[o * 128 + 96 + s] * sh_pos[s * 49 + hm * 7 + wm];
        }
        g_D[p] = d;
    } else if (blk < 32) {
        int p = (blk - 16) * 256 + tid;  // < 4096
        int o = p >> 6, k = p & 63;
        float a = c2w[o * 64 + k];
        #pragma unroll 8
        for (int m = 0; m < 64; m++) a += fw[o * 128 + m] * c2w[m * 64 + k];
        g_AT[k * 64 + o] = a;
    } else if (blk < 60) {
        int idx = (blk - 32) * 256 + tid;
        if (idx < 12 * 9 * 64) {
            int c = idx / (9 * 64), t = (idx / 64) % 9, o = idx & 63;
            g_TW[idx] = (c < 11) ? c1w[o * 99 + c * 9 + t] : 0.f;
        }
    } else {
        int idx = (blk - 60) * 256 + tid;  // < 8192
        int b = idx >> 8, ty = (idx >> 4) & 15, tx = idx & 15;
        const float* px = x + (long long)b * 11 * 16384 + (ty * 8) * 128 + (tx * 8);
        int best = 0; float bv = px[0];
        for (int c = 1; c < 11; c++) {
            float v = px[(long long)c * 16384];
            if (v > bv) { bv = v; best = c; }
        }
        g_lab[idx] = best;
    }
}

// ================= K2: tables + corners, AT staged in shared =================
// blocks 0..890: tables (4 entries each, 3564 total)
// blocks 891..2690: corner pixels (4 each, 7200 total)
__global__ void k2_kernel(const float* __restrict__ c1b, float* __restrict__ out) {
    __shared__ float sAT[64 * 64];
    __shared__ float sy[4][64];
    int tid = threadIdx.x;
    #pragma unroll
    for (int i = 0; i < 16; i++) sAT[i * 256 + tid] = g_AT[i * 256 + tid];

    int el = tid >> 6, o = tid & 63;
    if (blockIdx.x < 891) {
        int e = blockIdx.x * 4 + el;
        int ht, wt, cc, cr = 11, cb = 11;
        float* dst;
        if (e < 972) {
            cc = e % 12; int r = e / 12;
            int wi = r % 9, hi = r / 9;
            wt = (wi == 8) ? 9 : wi;
            ht = (hi == 8) ? 9 : hi;
            dst = &g_Fs[((ht * 10 + wt) * 12 + cc) * 64];
        } else if (e < 972 + 1296) {
            int r = e - 972;
            cb = r % 12; r /= 12; cc = r % 12;
            int wi = r / 12; wt = (wi == 8) ? 9 : wi; ht = 8;
            dst = &g_Fr[((wt * 12 + cc) * 12 + cb) * 64];
        } else {
            int r = e - 972 - 1296;
            cr = r % 12; r /= 12; cc = r % 12;
            int hi = r / 12; ht = (hi == 8) ? 9 : hi; wt = 8;
            dst = &g_Fc[((ht * 12 + cc) * 12 + cr) * 64];
        }
        float y = c1b[o];
        #pragma unroll
        for (int dy = 0; dy < 3; dy++)
            #pragma unroll
            for (int dx = 0; dx < 3; dx++) {
                int rk = c_rk[ht][dy], ck = c_rk[wt][dx];
                int cls = cellcls(rk, ck, cc, cr, cb, 11);
                y += g_TW[(cls * 9 + dy * 3 + dx) * 64 + o];
            }
        sy[el][o] = fmaxf(y, 0.f);
        __syncthreads();
        int hm = hm_of(ht), wm = hm_of(wt);
        float acc = g_D[(hm * 8 + wm) * 64 + o];
        #pragma unroll 16
        for (int k = 0; k < 64; k++) acc += sAT[k * 64 + o] * sy[el][k];
        dst[o] = acc;
    } else {
        int e = (blockIdx.x - 891) * 4 + el;  // < 7200
        int b = e / 225, r = e % 225, ti = r / 15, tj = r % 15;
        int labbase = (b << 8) + (ti << 4) + tj;
        int cc = g_lab[labbase], cr = g_lab[labbase + 1];
        int cb = g_lab[labbase + 16], cd = g_lab[labbase + 17];
        float y = c1b[o];
        #pragma unroll
        for (int dy = 0; dy < 3; dy++)
            #pragma unroll
            for (int dx = 0; dx < 3; dx++) {
                int rk = c_rk[8][dy], ck = c_rk[8][dx];
                int cls = cellcls(rk, ck, cc, cr, cb, cd);
                y += g_TW[(cls * 9 + dy * 3 + dx) * 64 + o];
            }
        sy[el][o] = fmaxf(y, 0.f);
        __syncthreads();
        float acc = g_D[(7 * 8 + 7) * 64 + o];
        #pragma unroll 16
        for (int k = 0; k < 64; k++) acc += sAT[k * 64 + o] * sy[el][k];
        int h = ti * 8 + 7, w = tj * 8 + 7;
        out[((long long)(b * 64 + o) << 14) + h * 128 + w] = acc;
    }
}

// ================= K3: main gather + write (4 lanes per pixel) =================
// thread = (pixel, part): part = tid&3 loads float4s q = part + 4i (i=0..3),
// i.e. channels c = 4*part + 16*i + j. Warp covers 8 consecutive pixels.
__global__ void main_kernel(float* __restrict__ out) {
    int tid = threadIdx.x;
    int gp = blockIdx.x * 64 + (tid >> 2);    // global pixel id
    int part = tid & 3;
    int b = gp >> 14, rem = gp & 16383, h = rem >> 7, w = rem & 127;
    int hm = h & 7, wm = w & 7;
    int ht = (hm == 0) ? (h == 0 ? 0 : 1) : (hm < 7 ? hm + 1 : (h == 127 ? 9 : 8));
    int wt = (wm == 0) ? (w == 0 ? 0 : 1) : (wm < 7 ? wm + 1 : (w == 127 ? 9 : 8));
    if (ht == 8 && wt == 8) return;           // corner pixels written by k2
    int ty = h >> 3, tx = w >> 3;
    int labbase = (b << 8) + (ty << 4) + tx;
    int cc = g_lab[labbase];
    const float4* F;
    if (ht == 8) {
        int cb = g_lab[labbase + 16];
        F = (const float4*)&g_Fr[((wt * 12 + cc) * 12 + cb) * 64];
    } else if (wt == 8) {
        int cr = g_lab[labbase + 1];
        F = (const float4*)&g_Fc[((ht * 12 + cc) * 12 + cr) * 64];
    } else {
        F = (const float4*)&g_Fs[((ht * 10 + wt) * 12 + cc) * 64];
    }
    float4 v0 = F[part];
    float4 v1 = F[part + 4];
    float4 v2 = F[part + 8];
    float4 v3 = F[part + 12];
    float* op = out + ((long long)b << 20) + rem + (long long)part * 4 * 16384;
    // channels: 4*part + 16*i + j  -> offset (16*i + j)*16384 from op
    op[0 * 16384] = v0.x; op[1 * 16384] = v0.y; op[2 * 16384] = v0.z; op[3 * 16384] = v0.w;
    op[16 * 16384] = v1.x; op[17 * 16384] = v1.y; op[18 * 16384] = v1.z; op[19 * 16384] = v1.w;
    op[32 * 16384] = v2.x; op[33 * 16384] = v2.y; op[34 * 16384] = v2.z; op[35 * 16384] = v2.w;
    op[48 * 16384] = v3.x; op[49 * 16384] = v3.y; op[50 * 16384] = v3.z; op[51 * 16384] = v3.w;
}

// ---------------- launch ----------------
extern "C" void kernel_launch(void* const* d_in, const int* in_sizes, int n_in,
                              void* d_out, int out_size) {
    const float* x   = (const float*)d_in[0];
    const float* c1w = (const float*)d_in[1];
    const float* c1b = (const float*)d_in[2];
    const float* c2w = (const float*)d_in[3];
    const float* c2b = (const float*)d_in[4];
    const float* sew = (const float*)d_in[5];
    const float* seb = (const float*)d_in[6];
    const float* slw = (const float*)d_in[7];
    const float* slb = (const float*)d_in[8];
    const float* rpw = (const float*)d_in[9];
    const float* rpb = (const float*)d_in[10];
    const float* fw  = (const float*)d_in[11];
    const float* fb  = (const float*)d_in[12];
    float* out = (float*)d_out;

    k1_kernel<<<92, 256>>>(x, c1w, c1b, c2w, c2b, sew, seb, slw, slb, rpw, rpb, fw, fb);
    k2_kernel<<<891 + 1800, 256>>>(c1b, out);
    main_kernel<<<8192, 256>>>(out);
}

// round 3
// speedup vs baseline: 3.0309x; 1.1037x over previous
#include <cuda_runtime.h>
#include <cuda_bf16.h>

// Problem constants: B=32, Cin=11, H=W=128, K=8, P=7, TN=16, ED=64, SD=32
// out: (32, 64, 128, 128) float32

// ---------------- static device scratch ----------------
__device__ __align__(256) float g_TW[12 * 9 * 64];        // tap weights per class (11 = pad = 0)
__device__ __align__(256) float g_AT[64 * 64];            // AT[k][o], A = (I+W1)@conv2_w
__device__ __align__(256) float g_D[8 * 8 * 64];          // D[hm][wm][o]
__device__ __align__(256) float g_Fs[10 * 10 * 12 * 64];  // [ht][wt][cc][o]
__device__ __align__(256) float g_Fr[10 * 12 * 12 * 64];  // ht==8: [wt][cc][cb][o]
__device__ __align__(256) float g_Fc[10 * 12 * 12 * 64];  // wt==8: [ht][cc][cr][o]
__device__ int   g_lab[32 * 16 * 16];

// row kinds per position type t (0..9): 0=PAD,1=ZERO,2=CUR,3=NEXT
__constant__ int c_rk[10][3] = {
    {0,2,2},{1,2,2},{2,2,2},{2,2,2},{2,2,2},{2,2,2},{2,2,2},{2,2,1},{2,1,3},{2,1,0}
};

__device__ __forceinline__ int cellcls(int rk, int ck, int cc, int cr, int cb, int cd) {
    if (rk == 0 || ck == 0) return 11;
    if (rk == 1 || ck == 1) return 0;
    if (rk == 2) return (ck == 2) ? cc : cr;
    return (ck == 2) ? cb : cd;
}
__device__ __forceinline__ int hm_of(int t) { return (t <= 1) ? 0 : ((t <= 7) ? t - 1 : 7); }

// ================= K1: setup (parallel, high-MLP) + labels =================
// blocks 0..31: labels | 32..47: AT | 48..63: D (+prolog) | 64..90: TW
__global__ __launch_bounds__(256) void k1_kernel(
    const float* __restrict__ x,
    const float* __restrict__ c1w, const float* __restrict__ c1b,
    const float* __restrict__ c2w, const float* __restrict__ c2b,
    const float* __restrict__ sew, const float* __restrict__ seb,
    const float* __restrict__ slw, const float* __restrict__ slb,
    const float* __restrict__ rpw, const float* __restrict__ rpb,
    const float* __restrict__ fw,  const float* __restrict__ fb)
{
    int tid = threadIdx.x;
    int blk = blockIdx.x;

    if (blk < 32) {
        // ---- labels: argmax over 11 one-hot channels at tile origin ----
        int idx = blk * 256 + tid;  // < 8192
        int b = idx >> 8, ty = (idx >> 4) & 15, tx = idx & 15;
        const float* px = x + (long long)b * 11 * 16384 + (ty * 8) * 128 + (tx * 8);
        float v[11];
        #pragma unroll
        for (int c = 0; c < 11; c++) v[c] = px[(long long)c * 16384];
        int best = 0; float bv = v[0];
        #pragma unroll
        for (int c = 1; c < 11; c++) { if (v[c] > bv) { bv = v[c]; best = c; } }
        g_lab[idx] = best;
    } else if (blk < 48) {
        // ---- AT[k][o] = conv2_w[o][k] + sum_m fus_w[o][m]*conv2_w[m][k] ----
        int p = (blk - 32) * 256 + tid;  // < 4096
        int o = p >> 6, k = p & 63;
        float a = c2w[o * 64 + k];
        #pragma unroll
        for (int m = 0; m < 64; m++) a += fw[o * 128 + m] * c2w[m * 64 + k];
        g_AT[k * 64 + o] = a;
    } else if (blk < 64) {
        // ---- D with parallel prolog ----
        __shared__ float sh_h[16 * 49];
        __shared__ float sh_p[256];
        __shared__ float sh_red[32][8];
        __shared__ float sh_sv[32];
        __shared__ float sh_pos[32 * 49];

        // se conv3x3 on all-ones 7x7 mask, pad=1, relu
        for (int idx = tid; idx < 16 * 49; idx += 256) {
            int c = idx / 49, r = (idx % 49) / 7, j = idx % 7;
            float v = seb[c];
            #pragma unroll
            for (int ky = 0; ky < 3; ky++)
                #pragma unroll
                for (int kx = 0; kx < 3; kx++) {
                    int rr = r - 1 + ky, ccol = j - 1 + kx;
                    if (rr >= 0 && rr < 7 && ccol >= 0 && ccol < 7) v += sew[c * 9 + ky * 3 + kx];
                }
            sh_h[idx] = fmaxf(v, 0.f);
        }
        __syncthreads();
        {   // adaptive maxpool 7->4
            int c = tid / 16, ri = (tid % 16) / 4, rj = tid % 4;
            const int s4[4] = {0, 1, 3, 5}, e4[4] = {2, 4, 6, 7};
            float m = -1e30f;
            for (int r = s4[ri]; r < e4[ri]; r++)
                for (int cc = s4[rj]; cc < e4[rj]; cc++)
                    m = fmaxf(m, sh_h[c * 49 + r * 7 + cc]);
            sh_p[tid] = m;
        }
        __syncthreads();
        {   // shape_vec partials: thread (s = tid>>3, chunk = tid&7) covers 32 terms
            int s = tid >> 3, c8 = tid & 7;
            const float* row = slw + s * 256 + c8 * 32;
            const float* pp = sh_p + c8 * 32;
            float acc = 0.f;
            #pragma unroll
            for (int u = 0; u < 32; u++) acc += row[u] * pp[u];
            sh_red[s][c8] = acc;
        }
        // pos map (independent of shape_vec)
        for (int idx = tid; idx < 32 * 49; idx += 256) {
            int s = idx / 49, i = (idx % 49) / 7, j = idx % 7;
            sh_pos[idx] = rpb[s] + rpw[s * 2] * (i / 6.0f) + rpw[s * 2 + 1] * (j / 6.0f);
        }
        __syncthreads();
        if (tid < 32) {
            float a = slb[tid];
            #pragma unroll
            for (int u = 0; u < 8; u++) a += sh_red[tid][u];
            sh_sv[tid] = fmaxf(a, 0.f);
        }
        __syncthreads();
        // D entry (one per thread), full unroll for MLP
        int p = (blk - 48) * 256 + tid;  // < 4096
        int hm = p >> 9, wm = (p >> 6) & 7, o = p & 63;
        float d = c2b[o] + fb[o];
        #pragma unroll
        for (int m = 0; m < 64; m++) d += fw[o * 128 + m] * c2b[m];
        if (hm < 7 && wm < 7) {
            #pragma unroll
            for (int s = 0; s < 32; s++) d += fw[o * 128 + 64 + s] * sh_sv[s];
            #pragma unroll
            for (int s = 0; s < 32; s++) d += fw[o * 128 + 96 + s] * sh_pos[s * 49 + hm * 7 + wm];
        }
        g_D[p] = d;
    } else {
        // ---- TW[class][tap][o] ----
        int idx = (blk - 64) * 256 + tid;
        if (idx < 12 * 9 * 64) {
            int c = idx / (9 * 64), t = (idx / 64) % 9, o = idx & 63;
            g_TW[idx] = (c < 11) ? c1w[o * 99 + c * 9 + t] : 0.f;
        }
    }
}

// ================= K2: tables + corners, 16 entries/block =================
// blocks 0..222: table entries (3564), blocks 223..672: corner pixels (7200)
__global__ __launch_bounds__(256) void k2_kernel(const float* __restrict__ c1b,
                                                 float* __restrict__ out) {
    __shared__ float sAT[64 * 64];
    __shared__ float sy[4][64];
    int tid = threadIdx.x;
    {   // stage AT (16KB) with float4 loads
        const float4* src = (const float4*)g_AT;
        float4* dst4 = (float4*)sAT;
        #pragma unroll
        for (int i = 0; i < 4; i++) dst4[i * 256 + tid] = src[i * 256 + tid];
    }
    __syncthreads();

    int el = tid >> 6, o = tid & 63;
    float bias = c1b[o];

    if (blockIdx.x < 223) {
        #pragma unroll 1
        for (int it = 0; it < 4; it++) {
            int e = blockIdx.x * 16 + it * 4 + el;
            int ht = 0, wt = 0, cc = 0, cr = 11, cb = 11;
            float* dst = nullptr;
            bool valid = (e < 3564);
            if (valid) {
                if (e < 972) {
                    cc = e % 12; int r = e / 12;
                    int wi = r % 9, hi = r / 9;
                    wt = (wi == 8) ? 9 : wi;
                    ht = (hi == 8) ? 9 : hi;
                    dst = &g_Fs[((ht * 10 + wt) * 12 + cc) * 64];
                } else if (e < 972 + 1296) {
                    int r = e - 972;
                    cb = r % 12; r /= 12; cc = r % 12;
                    int wi = r / 12; wt = (wi == 8) ? 9 : wi; ht = 8;
                    dst = &g_Fr[((wt * 12 + cc) * 12 + cb) * 64];
                } else {
                    int r = e - 972 - 1296;
                    cr = r % 12; r /= 12; cc = r % 12;
                    int hi = r / 12; ht = (hi == 8) ? 9 : hi; wt = 8;
                    dst = &g_Fc[((ht * 12 + cc) * 12 + cr) * 64];
                }
                float y = bias;
                #pragma unroll
                for (int dy = 0; dy < 3; dy++)
                    #pragma unroll
                    for (int dx = 0; dx < 3; dx++) {
                        int rk = c_rk[ht][dy], ck = c_rk[wt][dx];
                        int cls = cellcls(rk, ck, cc, cr, cb, 11);
                        y += g_TW[(cls * 9 + dy * 3 + dx) * 64 + o];
                    }
                sy[el][o] = fmaxf(y, 0.f);
            }
            __syncthreads();
            if (valid) {
                int hm = hm_of(ht), wm = hm_of(wt);
                float acc = g_D[(hm * 8 + wm) * 64 + o];
                #pragma unroll
                for (int k = 0; k < 64; k++) acc += sAT[k * 64 + o] * sy[el][k];
                dst[o] = acc;
            }
            __syncthreads();
        }
    } else {
        #pragma unroll 1
        for (int it = 0; it < 4; it++) {
            int e = (blockIdx.x - 223) * 16 + it * 4 + el;  // < 7200
            int b = e / 225, r = e % 225, ti = r / 15, tj = r % 15;
            int labbase = (b << 8) + (ti << 4) + tj;
            int cc = g_lab[labbase], cr = g_lab[labbase + 1];
            int cb = g_lab[labbase + 16], cd = g_lab[labbase + 17];
            float y = bias;
            #pragma unroll
            for (int dy = 0; dy < 3; dy++)
                #pragma unroll
                for (int dx = 0; dx < 3; dx++) {
                    int rk = c_rk[8][dy], ck = c_rk[8][dx];
                    int cls = cellcls(rk, ck, cc, cr, cb, cd);
                    y += g_TW[(cls * 9 + dy * 3 + dx) * 64 + o];
                }
            sy[el][o] = fmaxf(y, 0.f);
            __syncthreads();
            float acc = g_D[(7 * 8 + 7) * 64 + o];
            #pragma unroll
            for (int k = 0; k < 64; k++) acc += sAT[k * 64 + o] * sy[el][k];
            int h = ti * 8 + 7, w = tj * 8 + 7;
            out[((long long)(b * 64 + o) << 14) + h * 128 + w] = acc;
            __syncthreads();
        }
    }
}

// ================= K3: main gather + write (4 lanes per pixel) =================
__global__ __launch_bounds__(256) void main_kernel(float* __restrict__ out) {
    int tid = threadIdx.x;
    int gp = blockIdx.x * 64 + (tid >> 2);    // global pixel id
    int part = tid & 3;
    int b = gp >> 14, rem = gp & 16383, h = rem >> 7, w = rem & 127;
    int hm = h & 7, wm = w & 7;
    int ht = (hm == 0) ? (h == 0 ? 0 : 1) : (hm < 7 ? hm + 1 : (h == 127 ? 9 : 8));
    int wt = (wm == 0) ? (w == 0 ? 0 : 1) : (wm < 7 ? wm + 1 : (w == 127 ? 9 : 8));
    if (ht == 8 && wt == 8) return;           // corner pixels written by k2
    int ty = h >> 3, tx = w >> 3;
    int labbase = (b << 8) + (ty << 4) + tx;
    int cc = g_lab[labbase];
    const float4* F;
    if (ht == 8) {
        int cb = g_lab[labbase + 16];
        F = (const float4*)&g_Fr[((wt * 12 + cc) * 12 + cb) * 64];
    } else if (wt == 8) {
        int cr = g_lab[labbase + 1];
        F = (const float4*)&g_Fc[((ht * 12 + cc) * 12 + cr) * 64];
    } else {
        F = (const float4*)&g_Fs[((ht * 10 + wt) * 12 + cc) * 64];
    }
    float4 v0 = F[part];
    float4 v1 = F[part + 4];
    float4 v2 = F[part + 8];
    float4 v3 = F[part + 12];
    float* op = out + ((long long)b << 20) + rem + (long long)part * 4 * 16384;
    op[0 * 16384] = v0.x;  op[1 * 16384] = v0.y;  op[2 * 16384] = v0.z;  op[3 * 16384] = v0.w;
    op[16 * 16384] = v1.x; op[17 * 16384] = v1.y; op[18 * 16384] = v1.z; op[19 * 16384] = v1.w;
    op[32 * 16384] = v2.x; op[33 * 16384] = v2.y; op[34 * 16384] = v2.z; op[35 * 16384] = v2.w;
    op[48 * 16384] = v3.x; op[49 * 16384] = v3.y; op[50 * 16384] = v3.z; op[51 * 16384] = v3.w;
}

// ---------------- launch ----------------
extern "C" void kernel_launch(void* const* d_in, const int* in_sizes, int n_in,
                              void* d_out, int out_size) {
    const float* x   = (const float*)d_in[0];
    const float* c1w = (const float*)d_in[1];
    const float* c1b = (const float*)d_in[2];
    const float* c2w = (const float*)d_in[3];
    const float* c2b = (const float*)d_in[4];
    const float* sew = (const float*)d_in[5];
    const float* seb = (const float*)d_in[6];
    const float* slw = (const float*)d_in[7];
    const float* slb = (const float*)d_in[8];
    const float* rpw = (const float*)d_in[9];
    const float* rpb = (const float*)d_in[10];
    const float* fw  = (const float*)d_in[11];
    const float* fb  = (const float*)d_in[12];
    float* out = (float*)d_out;

    k1_kernel<<<91, 256>>>(x, c1w, c1b, c2w, c2b, sew, seb, slw, slb, rpw, rpb, fw, fb);
    k2_kernel<<<673, 256>>>(c1b, out);
    main_kernel<<<8192, 256>>>(out);
}

// round 4
// speedup vs baseline: 3.9025x; 1.2876x over previous
#include <cuda_runtime.h>
#include <cuda_bf16.h>

// Problem constants: B=32, Cin=11, H=W=128, K=8, P=7, TN=16, ED=64, SD=32
// out: (32, 64, 128, 128) float32

// ---------------- static device scratch ----------------
__device__ __align__(256) float g_TW[12 * 9 * 64];        // tap weights per class (11 = pad = 0)
__device__ __align__(256) float g_AT[64 * 64];            // AT[k][o], A = (I+W1)@conv2_w
__device__ __align__(256) float g_D[8 * 8 * 64];          // D[hm*8+wm][o]
__device__ __align__(256) float g_Fs[10 * 10 * 12 * 64];  // [ht][wt][cc][o]
__device__ __align__(256) float g_Fr[10 * 12 * 12 * 64];  // ht==8: [wt][cc][cb][o]
__device__ __align__(256) float g_Fc[10 * 12 * 12 * 64];  // wt==8: [ht][cc][cr][o]
__device__ int   g_lab[32 * 16 * 16];

// row kinds per position type t (0..9): 0=PAD,1=ZERO,2=CUR,3=NEXT
__constant__ int c_rk[10][3] = {
    {0,2,2},{1,2,2},{2,2,2},{2,2,2},{2,2,2},{2,2,2},{2,2,2},{2,2,1},{2,1,3},{2,1,0}
};

__device__ __forceinline__ int cellcls(int rk, int ck, int cc, int cr, int cb, int cd) {
    if (rk == 0 || ck == 0) return 11;
    if (rk == 1 || ck == 1) return 0;
    if (rk == 2) return (ck == 2) ? cc : cr;
    return (ck == 2) ? cb : cd;
}
__device__ __forceinline__ int hm_of(int t) { return (t <= 1) ? 0 : ((t <= 7) ? t - 1 : 7); }

// ================= K1: setup (coalesced, staged in shared) + labels =================
// blocks 0..31: labels | 32..47: AT | 48..63: D (+prolog) | 64..90: TW
__global__ __launch_bounds__(256) void k1_kernel(
    const float* __restrict__ x,
    const float* __restrict__ c1w, const float* __restrict__ c1b,
    const float* __restrict__ c2w, const float* __restrict__ c2b,
    const float* __restrict__ sew, const float* __restrict__ seb,
    const float* __restrict__ slw, const float* __restrict__ slb,
    const float* __restrict__ rpw, const float* __restrict__ rpb,
    const float* __restrict__ fw,  const float* __restrict__ fb)
{
    __shared__ __align__(16) float smem[9600];
    int tid = threadIdx.x;
    int blk = blockIdx.x;

    if (blk < 32) {
        // ---- labels: argmax over 11 one-hot channels at tile origin ----
        int idx = blk * 256 + tid;  // < 8192
        int b = idx >> 8, ty = (idx >> 4) & 15, tx = idx & 15;
        const float* px = x + (long long)b * 11 * 16384 + (ty * 8) * 128 + (tx * 8);
        float v[11];
        #pragma unroll
        for (int c = 0; c < 11; c++) v[c] = px[(long long)c * 16384];
        int best = 0; float bv = v[0];
        #pragma unroll
        for (int c = 1; c < 11; c++) { if (v[c] > bv) { bv = v[c]; best = c; } }
        g_lab[idx] = best;
    } else if (blk < 48) {
        // ---- AT[k][o] = conv2_w[o][k] + sum_m fus_w[o][m]*conv2_w[m][k] ----
        float* sc2w = smem;          // 4096 floats: [m*64+k]
        float* sfw4 = smem + 4096;   // 512 floats: 4 fw rows of this block
        int o0 = (blk - 32) * 4;
        {   // stage c2w coalesced
            const float4* src = (const float4*)c2w;
            float4* dst = (float4*)sc2w;
            #pragma unroll
            for (int i = 0; i < 4; i++) dst[i * 256 + tid] = src[i * 256 + tid];
            // stage fw rows o0..o0+3 (512 floats = 128 float4)
            if (tid < 128) ((float4*)sfw4)[tid] = ((const float4*)(fw + o0 * 128))[tid];
        }
        __syncthreads();
        int ol = tid >> 6, k = tid & 63;
        int o = o0 + ol;
        float a = sc2w[o * 64 + k];
        #pragma unroll
        for (int m = 0; m < 64; m++) a += sfw4[ol * 128 + m] * sc2w[m * 64 + k];
        g_AT[k * 64 + o] = a;
    } else if (blk < 64) {
        // ---- D with staged fw (pitch 129) + parallel prolog ----
        float* sfw  = smem;                 // 64 rows * pitch 129 = 8256 floats
        float* sh_h = smem + 8256;          // 784
        float* sh_p = sh_h + 784;           // 256  (16B aligned: offset 9040*4)
        float* sh_sv = sh_p + 256;          // 32
        float* sc2b = sh_sv + 32;           // 64
        float* srpb = sc2b + 64;            // 32
        float* srpw = srpb + 32;            // 64

        // stage fw with pitch-129 layout (coalesced reads, 4-way-conflict scalar writes)
        {
            const float4* fw4 = (const float4*)fw;
            #pragma unroll
            for (int it = 0; it < 8; it++) {
                int f = it * 256 + tid;          // float4 index < 2048
                float4 v = fw4[f];
                int o = f >> 5, j4 = (f & 31) * 4;
                float* d = sfw + o * 129 + j4;
                d[0] = v.x; d[1] = v.y; d[2] = v.z; d[3] = v.w;
            }
        }
        // conv3x3 on all-ones 7x7 mask, pad=1, relu
        for (int idx = tid; idx < 784; idx += 256) {
            int c = idx / 49, r = (idx % 49) / 7, j = idx % 7;
            float v = seb[c];
            #pragma unroll
            for (int ky = 0; ky < 3; ky++)
                #pragma unroll
                for (int kx = 0; kx < 3; kx++) {
                    int rr = r - 1 + ky, ccol = j - 1 + kx;
                    if (rr >= 0 && rr < 7 && ccol >= 0 && ccol < 7) v += sew[c * 9 + ky * 3 + kx];
                }
            sh_h[idx] = fmaxf(v, 0.f);
        }
        if (tid < 64) sc2b[tid] = c2b[tid];
        if (tid < 32) srpb[tid] = rpb[tid];
        if (tid < 64) srpw[tid] = rpw[tid];
        __syncthreads();
        {   // adaptive maxpool 7->4
            int c = tid / 16, ri = (tid % 16) / 4, rj = tid % 4;
            const int s4[4] = {0, 1, 3, 5}, e4[4] = {2, 4, 6, 7};
            float m = -1e30f;
            for (int r = s4[ri]; r < e4[ri]; r++)
                for (int cc = s4[rj]; cc < e4[rj]; cc++)
                    m = fmaxf(m, sh_h[c * 49 + r * 7 + cc]);
            sh_p[tid] = m;
        }
        __syncthreads();
        {   // shape_vec: warp w handles rows s = 4w..4w+3 (coalesced f4 + shuffle reduce)
            int warp = tid >> 5, lane = tid & 31;
            const float4* p4 = (const float4*)sh_p;
            float4 pa = p4[lane], pb = p4[lane + 32];
            #pragma unroll
            for (int si = 0; si < 4; si++) {
                int s = warp * 4 + si;
                const float4* row = (const float4*)(slw + s * 256);
                float4 ra = row[lane], rb = row[lane + 32];
                float part = ra.x * pa.x + ra.y * pa.y + ra.z * pa.z + ra.w * pa.w
                           + rb.x * pb.x + rb.y * pb.y + rb.z * pb.z + rb.w * pb.w;
                #pragma unroll
                for (int off = 16; off > 0; off >>= 1)
                    part += __shfl_down_sync(0xffffffffu, part, off);
                if (lane == 0) sh_sv[s] = fmaxf(part + slb[s], 0.f);
            }
        }
        __syncthreads();
        // D entry (one per thread): o = lane-consecutive -> conflict-free pitch-129 reads
        int p = (blk - 48) * 256 + tid;  // < 4096
        int hw = p >> 6, o = p & 63, hm = hw >> 3, wm = hw & 7;
        float d = sc2b[o] + fb[o];
        #pragma unroll
        for (int m = 0; m < 64; m++) d += sfw[o * 129 + m] * sc2b[m];
        if (hm < 7 && wm < 7) {
            float fi = hm * (1.0f / 6.0f), fj = wm * (1.0f / 6.0f);
            #pragma unroll
            for (int s = 0; s < 32; s++) d += sfw[o * 129 + 64 + s] * sh_sv[s];
            #pragma unroll
            for (int s = 0; s < 32; s++)
                d += sfw[o * 129 + 96 + s] * (srpb[s] + srpw[2 * s] * fi + srpw[2 * s + 1] * fj);
        }
        g_D[hw * 64 + o] = d;
    } else {
        // ---- TW[class][tap][o] ----
        int idx = (blk - 64) * 256 + tid;
        if (idx < 12 * 9 * 64) {
            int c = idx / (9 * 64), t = (idx / 64) % 9, o = idx & 63;
            g_TW[idx] = (c < 11) ? c1w[o * 99 + c * 9 + t] : 0.f;
        }
    }
}

// ================= K2: tables + corners, 32 entries/block =================
// blocks 0..111: table entries (3564), blocks 112..336: corner pixels (7200)
__global__ __launch_bounds__(256) void k2_kernel(const float* __restrict__ c1b,
                                                 float* __restrict__ out) {
    __shared__ float sAT[64 * 64];
    __shared__ float sy[4][64];
    int tid = threadIdx.x;
    {   // stage AT (16KB) with float4 loads
        const float4* src = (const float4*)g_AT;
        float4* dst4 = (float4*)sAT;
        #pragma unroll
        for (int i = 0; i < 4; i++) dst4[i * 256 + tid] = src[i * 256 + tid];
    }
    __syncthreads();

    int el = tid >> 6, o = tid & 63;
    float bias = c1b[o];

    if (blockIdx.x < 112) {
        #pragma unroll 1
        for (int it = 0; it < 8; it++) {
            int e = blockIdx.x * 32 + it * 4 + el;
            int ht = 0, wt = 0, cc = 0, cr = 11, cb = 11;
            float* dst = nullptr;
            bool valid = (e < 3564);
            if (valid) {
                if (e < 972) {
                    cc = e % 12; int r = e / 12;
                    int wi = r % 9, hi = r / 9;
                    wt = (wi == 8) ? 9 : wi;
                    ht = (hi == 8) ? 9 : hi;
                    dst = &g_Fs[((ht * 10 + wt) * 12 + cc) * 64];
                } else if (e < 972 + 1296) {
                    int r = e - 972;
                    cb = r % 12; r /= 12; cc = r % 12;
                    int wi = r / 12; wt = (wi == 8) ? 9 : wi; ht = 8;
                    dst = &g_Fr[((wt * 12 + cc) * 12 + cb) * 64];
                } else {
                    int r = e - 972 - 1296;
                    cr = r % 12; r /= 12; cc = r % 12;
                    int hi = r / 12; ht = (hi == 8) ? 9 : hi; wt = 8;
                    dst = &g_Fc[((ht * 12 + cc) * 12 + cr) * 64];
                }
                float y = bias;
                #pragma unroll
                for (int dy = 0; dy < 3; dy++)
                    #pragma unroll
                    for (int dx = 0; dx < 3; dx++) {
                        int rk = c_rk[ht][dy], ck = c_rk[wt][dx];
                        int cls = cellcls(rk, ck, cc, cr, cb, 11);
                        y += g_TW[(cls * 9 + dy * 3 + dx) * 64 + o];
                    }
                sy[el][o] = fmaxf(y, 0.f);
            }
            __syncthreads();
            if (valid) {
                int hm = hm_of(ht), wm = hm_of(wt);
                float acc = g_D[(hm * 8 + wm) * 64 + o];
                #pragma unroll
                for (int k = 0; k < 64; k++) acc += sAT[k * 64 + o] * sy[el][k];
                dst[o] = acc;
            }
            __syncthreads();
        }
    } else {
        #pragma unroll 1
        for (int it = 0; it < 8; it++) {
            int e = (blockIdx.x - 112) * 32 + it * 4 + el;  // < 7200 exactly
            int b = e / 225, r = e % 225, ti = r / 15, tj = r % 15;
            int labbase = (b << 8) + (ti << 4) + tj;
            int cc = g_lab[labbase], cr = g_lab[labbase + 1];
            int cb = g_lab[labbase + 16], cd = g_lab[labbase + 17];
            float y = bias;
            #pragma unroll
            for (int dy = 0; dy < 3; dy++)
                #pragma unroll
                for (int dx = 0; dx < 3; dx++) {
                    int rk = c_rk[8][dy], ck = c_rk[8][dx];
                    int cls = cellcls(rk, ck, cc, cr, cb, cd);
                    y += g_TW[(cls * 9 + dy * 3 + dx) * 64 + o];
                }
            sy[el][o] = fmaxf(y, 0.f);
            __syncthreads();
            float acc = g_D[(7 * 8 + 7) * 64 + o];
            #pragma unroll
            for (int k = 0; k < 64; k++) acc += sAT[k * 64 + o] * sy[el][k];
            int h = ti * 8 + 7, w = tj * 8 + 7;
            out[((long long)(b * 64 + o) << 14) + h * 128 + w] = acc;
            __syncthreads();
        }
    }
}

// ================= K3: main gather + write (4 lanes per pixel) =================
__global__ __launch_bounds__(256) void main_kernel(float* __restrict__ out) {
    int tid = threadIdx.x;
    int gp = blockIdx.x * 64 + (tid >> 2);    // global pixel id
    int part = tid & 3;
    int b = gp >> 14, rem = gp & 16383, h = rem >> 7, w = rem & 127;
    int hm = h & 7, wm = w & 7;
    int ht = (hm == 0) ? (h == 0 ? 0 : 1) : (hm < 7 ? hm + 1 : (h == 127 ? 9 : 8));
    int wt = (wm == 0) ? (w == 0 ? 0 : 1) : (wm < 7 ? wm + 1 : (w == 127 ? 9 : 8));
    if (ht == 8 && wt == 8) return;           // corner pixels written by k2
    int ty = h >> 3, tx = w >> 3;
    int labbase = (b << 8) + (ty << 4) + tx;
    int cc = g_lab[labbase];
    const float4* F;
    if (ht == 8) {
        int cb = g_lab[labbase + 16];
        F = (const float4*)&g_Fr[((wt * 12 + cc) * 12 + cb) * 64];
    } else if (wt == 8) {
        int cr = g_lab[labbase + 1];
        F = (const float4*)&g_Fc[((ht * 12 + cc) * 12 + cr) * 64];
    } else {
        F = (const float4*)&g_Fs[((ht * 10 + wt) * 12 + cc) * 64];
    }
    float4 v0 = F[part];
    float4 v1 = F[part + 4];
    float4 v2 = F[part + 8];
    float4 v3 = F[part + 12];
    float* op = out + ((long long)b << 20) + rem + (long long)part * 4 * 16384;
    op[0 * 16384] = v0.x;  op[1 * 16384] = v0.y;  op[2 * 16384] = v0.z;  op[3 * 16384] = v0.w;
    op[16 * 16384] = v1.x; op[17 * 16384] = v1.y; op[18 * 16384] = v1.z; op[19 * 16384] = v1.w;
    op[32 * 16384] = v2.x; op[33 * 16384] = v2.y; op[34 * 16384] = v2.z; op[35 * 16384] = v2.w;
    op[48 * 16384] = v3.x; op[49 * 16384] = v3.y; op[50 * 16384] = v3.z; op[51 * 16384] = v3.w;
}

// ---------------- launch ----------------
extern "C" void kernel_launch(void* const* d_in, const int* in_sizes, int n_in,
                              void* d_out, int out_size) {
    const float* x   = (const float*)d_in[0];
    const float* c1w = (const float*)d_in[1];
    const float* c1b = (const float*)d_in[2];
    const float* c2w = (const float*)d_in[3];
    const float* c2b = (const float*)d_in[4];
    const float* sew = (const float*)d_in[5];
    const float* seb = (const float*)d_in[6];
    const float* slw = (const float*)d_in[7];
    const float* slb = (const float*)d_in[8];
    const float* rpw = (const float*)d_in[9];
    const float* rpb = (const float*)d_in[10];
    const float* fus_w = (const float*)d_in[11];
    const float* fus_b = (const float*)d_in[12];
    float* out = (float*)d_out;

    k1_kernel<<<91, 256>>>(x, c1w, c1b, c2w, c2b, sew, seb, slw, slb, rpw, rpb, fus_w, fus_b);
    k2_kernel<<<337, 256>>>(c1b, out);
    main_kernel<<<8192, 256>>>(out);
}